// round 1
// baseline (speedup 1.0000x reference)
#include <cuda_runtime.h>
#include <math.h>
#include <float.h>

#define NN   50000
#define NE   400000
#define NEF  450000    // NE + NN self loops
#define FIN  128
#define HC   256
#define NH   4
#define CD   64
#define EDIM 16
#define NGRP 64
#define NOUT 10

// ---------------- scratch (device globals; no allocation allowed) ----------
static __device__ __align__(16) float g_x[NN * HC];     // layer input (layers 2,3)
static __device__ __align__(16) float g_h[NN * HC];     // h = X @ W
static __device__ __align__(16) float g_agg[NN * HC];   // aggregation target
static __device__ __align__(16) float g_add[NN * HC];   // residual accumulator
static __device__ float g_mea[NN * EDIM];               // mean edge_attr per dst
static __device__ float g_deg[NN];
static __device__ float g_als[NN * NH];
static __device__ float g_ald[NN * NH];
static __device__ float g_m[NN * NH];
static __device__ float g_den[NN * NH];
static __device__ float g_alpha[(size_t)NEF * NH];
static __device__ float g_weeff[EDIM * NH];
static __device__ float g_t[NN];
static __device__ float g_score[NN];
static __device__ int   g_gstart[NGRP + 1];
static __device__ int   g_perm[NN];

// ---------------- helpers ---------------------------------------------------
__device__ __forceinline__ float atomicMaxF(float* addr, float v) {
    int* ia = (int*)addr;
    int old = *ia;
    while (__int_as_float(old) < v) {
        int assumed = old;
        old = atomicCAS(ia, assumed, __float_as_int(v));
        if (old == assumed) break;
    }
    return __int_as_float(old);
}

// ---------------- prologue: degree + mean edge_attr -------------------------
__global__ void k_init0() {
    int i = blockIdx.x * blockDim.x + threadIdx.x;
    if (i < NN * EDIM) g_mea[i] = 0.f;
    if (i < NN) g_deg[i] = 0.f;
}
__global__ void k_deg(const int* __restrict__ dst) {
    int e = blockIdx.x * blockDim.x + threadIdx.x;
    if (e < NE) atomicAdd(&g_deg[dst[e]], 1.f);
}
__global__ void k_measum(const int* __restrict__ dst, const float* __restrict__ ea) {
    int i = blockIdx.x * blockDim.x + threadIdx.x;
    if (i >= NE * EDIM) return;
    int e = i >> 4, j = i & 15;
    atomicAdd(&g_mea[dst[e] * EDIM + j], ea[i]);
}
__global__ void k_meadiv() {
    int i = blockIdx.x * blockDim.x + threadIdx.x;
    if (i >= NN * EDIM) return;
    g_mea[i] /= fmaxf(g_deg[i >> 4], 1.f);
}

// ---------------- per-layer init --------------------------------------------
__global__ void k_layerinit() {
    int i = blockIdx.x * blockDim.x + threadIdx.x;
    if (i < NN * HC) g_agg[i] = 0.f;
    if (i < NN * NH) { g_m[i] = -FLT_MAX; g_den[i] = 0.f; }
}

// ---------------- GEMM: g_h = A[M,K] @ W[K,HC] ------------------------------
__global__ void k_gemm(const float* __restrict__ A, const float* __restrict__ W, int K) {
    const int BM = 64, BN = 64, BK = 16;
    __shared__ float As[BK][BM];
    __shared__ float Bs[BK][BN];
    int bx = blockIdx.x;        // column tile (HC/64 = 4)
    int by = blockIdx.y;        // row tile
    int tid = threadIdx.x;
    int tx = tid & 15, ty = tid >> 4;
    int rowBase = by * BM;
    int a_r = tid >> 2, a_c = (tid & 3) * 4;
    int b_r = tid >> 4, b_c = (tid & 15) * 4;
    float acc[4][4] = {};
    for (int k0 = 0; k0 < K; k0 += BK) {
        float4 av = make_float4(0.f, 0.f, 0.f, 0.f);
        int gr = rowBase + a_r;
        if (gr < NN) av = *(const float4*)&A[(size_t)gr * K + k0 + a_c];
        As[a_c + 0][a_r] = av.x; As[a_c + 1][a_r] = av.y;
        As[a_c + 2][a_r] = av.z; As[a_c + 3][a_r] = av.w;
        float4 bv = *(const float4*)&W[(size_t)(k0 + b_r) * HC + bx * BN + b_c];
        *(float4*)&Bs[b_r][b_c] = bv;
        __syncthreads();
#pragma unroll
        for (int kk = 0; kk < BK; kk++) {
            float ar[4], br[4];
#pragma unroll
            for (int i = 0; i < 4; i++) ar[i] = As[kk][ty * 4 + i];
#pragma unroll
            for (int j = 0; j < 4; j++) br[j] = Bs[kk][tx * 4 + j];
#pragma unroll
            for (int i = 0; i < 4; i++)
#pragma unroll
                for (int j = 0; j < 4; j++) acc[i][j] += ar[i] * br[j];
        }
        __syncthreads();
    }
#pragma unroll
    for (int i = 0; i < 4; i++) {
        int gr = rowBase + ty * 4 + i;
        if (gr < NN) {
            float4 v = make_float4(acc[i][0], acc[i][1], acc[i][2], acc[i][3]);
            *(float4*)&g_h[(size_t)gr * HC + bx * BN + tx * 4] = v;
        }
    }
}

// ---------------- effective edge weights: weeff[d][h] = sum_c We[d,h*C+c]*ae[h,c]
__global__ void k_weeff(const float* __restrict__ We, const float* __restrict__ ae) {
    int tid = threadIdx.x;
    if (tid >= EDIM * NH) return;
    int d = tid >> 2, h = tid & 3;
    float s = 0.f;
    for (int c = 0; c < CD; c++) s += We[d * HC + h * CD + c] * ae[h * CD + c];
    g_weeff[d * NH + h] = s;
}

// ---------------- per-node attention logits ---------------------------------
__global__ void k_alsd(const float* __restrict__ as_, const float* __restrict__ ad_) {
    int n = (blockIdx.x * blockDim.x + threadIdx.x) >> 5;
    int lane = threadIdx.x & 31;
    if (n >= NN) return;
    size_t base = (size_t)n * HC;
#pragma unroll
    for (int h = 0; h < NH; h++) {
        int o = h * CD + lane;
        float vs = g_h[base + o] * as_[o] + g_h[base + o + 32] * as_[o + 32];
        float vd = g_h[base + o] * ad_[o] + g_h[base + o + 32] * ad_[o + 32];
#pragma unroll
        for (int s = 16; s > 0; s >>= 1) {
            vs += __shfl_xor_sync(0xFFFFFFFFu, vs, s);
            vd += __shfl_xor_sync(0xFFFFFFFFu, vd, s);
        }
        if (lane == 0) { g_als[n * NH + h] = vs; g_ald[n * NH + h] = vd; }
    }
}

// ---------------- edge logits + segment max ---------------------------------
__global__ void k_alpha(const int* __restrict__ src, const int* __restrict__ dst,
                        const float* __restrict__ ea) {
    int e = blockIdx.x * blockDim.x + threadIdx.x;
    if (e >= NEF) return;
    int s, d;
    const float* eap;
    if (e < NE) { s = src[e]; d = dst[e]; eap = ea + (size_t)e * EDIM; }
    else        { s = d = e - NE; eap = g_mea + (size_t)(e - NE) * EDIM; }
    float ale[NH] = {0.f, 0.f, 0.f, 0.f};
#pragma unroll
    for (int dd = 0; dd < EDIM; dd++) {
        float v = eap[dd];
#pragma unroll
        for (int h = 0; h < NH; h++) ale[h] += v * g_weeff[dd * NH + h];
    }
#pragma unroll
    for (int h = 0; h < NH; h++) {
        float a = g_als[s * NH + h] + g_ald[d * NH + h] + ale[h];
        a = (a > 0.f) ? a : 0.2f * a;
        g_alpha[(size_t)e * NH + h] = a;
        atomicMaxF(&g_m[d * NH + h], a);
    }
}

// ---------------- exp + segment sum ------------------------------------------
__global__ void k_exp(const int* __restrict__ dst) {
    int i = blockIdx.x * blockDim.x + threadIdx.x;
    if (i >= NEF * NH) return;
    int e = i >> 2, h = i & 3;
    int d = (e < NE) ? dst[e] : (e - NE);
    float ex = expf(g_alpha[i] - g_m[d * NH + h]);
    g_alpha[i] = ex;
    atomicAdd(&g_den[d * NH + h], ex);
}

// ---------------- weighted scatter aggregation (warp per edge) --------------
__global__ void k_aggr(const int* __restrict__ src, const int* __restrict__ dst) {
    int e = (blockIdx.x * blockDim.x + threadIdx.x) >> 5;
    int lane = threadIdx.x & 31;
    if (e >= NEF) return;
    int s, d;
    if (e < NE) { s = src[e]; d = dst[e]; } else { s = d = e - NE; }
    int hh = lane >> 3;
    float w = g_alpha[(size_t)e * NH + hh] / (g_den[d * NH + hh] + 1e-16f);
    const float4* hp = (const float4*)&g_h[(size_t)s * HC + lane * 8];
    float4 v0 = hp[0], v1 = hp[1];
    float* op = &g_agg[(size_t)d * HC + lane * 8];
    atomicAdd(op + 0, v0.x * w); atomicAdd(op + 1, v0.y * w);
    atomicAdd(op + 2, v0.z * w); atomicAdd(op + 3, v0.w * w);
    atomicAdd(op + 4, v1.x * w); atomicAdd(op + 5, v1.y * w);
    atomicAdd(op + 6, v1.z * w); atomicAdd(op + 7, v1.w * w);
}

// ---------------- bias + relu + residual ------------------------------------
__global__ void k_post(const float* __restrict__ b, int first) {
    int i = blockIdx.x * blockDim.x + threadIdx.x;
    if (i >= NN * HC) return;
    float v = g_agg[i] + b[i & (HC - 1)];
    v = fmaxf(v, 0.f);
    g_x[i] = v;
    g_add[i] = first ? v : (g_add[i] + v);
}

// ---------------- SAGPool score ----------------------------------------------
__global__ void k_tr(const float* __restrict__ wrel, const float* __restrict__ brel,
                     const float* __restrict__ wroot) {
    int n = (blockIdx.x * blockDim.x + threadIdx.x) >> 5;
    int lane = threadIdx.x & 31;
    if (n >= NN) return;
    size_t base = (size_t)n * HC;
    float t = 0.f, r = 0.f;
#pragma unroll
    for (int k = 0; k < 8; k++) {
        int c = lane + 32 * k;
        float v = g_add[base + c];
        t += v * wrel[c];
        r += v * wroot[c];
    }
#pragma unroll
    for (int s = 16; s > 0; s >>= 1) {
        t += __shfl_xor_sync(0xFFFFFFFFu, t, s);
        r += __shfl_xor_sync(0xFFFFFFFFu, r, s);
    }
    if (lane == 0) { g_t[n] = t; g_score[n] = r + brel[0]; }
}
__global__ void k_scoreedge(const int* __restrict__ src, const int* __restrict__ dst) {
    int e = blockIdx.x * blockDim.x + threadIdx.x;
    if (e < NE) atomicAdd(&g_score[dst[e]], g_t[src[e]]);
}

// ---------------- group boundaries (batch is sorted) --------------------------
__global__ void k_gstart(const int* __restrict__ batch) {
    int n = blockIdx.x * blockDim.x + threadIdx.x;
    if (n >= NN) return;
    int b = batch[n];
    int prev = (n == 0) ? -1 : batch[n - 1];
    for (int g = prev + 1; g <= b; g++) g_gstart[g] = n;
    if (n == NN - 1) {
        for (int g = b + 1; g <= NGRP; g++) g_gstart[g] = NN;
    }
}

// ---------------- per-group bitonic sort (descending score, tie: asc index) --
#define SORTP 2048
__global__ void k_sort() {
    __shared__ float sk[SORTP];
    __shared__ int   sv[SORTP];
    int g = blockIdx.x;
    int start = g_gstart[g], end = g_gstart[g + 1];
    int sz = end - start;
    if (sz > SORTP) sz = SORTP;  // cannot happen at these sizes
    for (int i = threadIdx.x; i < SORTP; i += blockDim.x) {
        if (i < sz) { sk[i] = g_score[start + i]; sv[i] = start + i; }
        else        { sk[i] = -FLT_MAX; sv[i] = 0x7FFFFFFF; }
    }
    __syncthreads();
    for (int k = 2; k <= SORTP; k <<= 1) {
        for (int j = k >> 1; j > 0; j >>= 1) {
            for (int i = threadIdx.x; i < SORTP; i += blockDim.x) {
                int ixj = i ^ j;
                if (ixj > i) {
                    float ki = sk[i], kj = sk[ixj];
                    int vi = sv[i], vj = sv[ixj];
                    bool before = (kj > ki) || (kj == ki && vj < vi);
                    bool dir = ((i & k) == 0);
                    if (before == dir) {
                        sk[i] = kj; sk[ixj] = ki;
                        sv[i] = vj; sv[ixj] = vi;
                    }
                }
            }
            __syncthreads();
        }
    }
    for (int i = threadIdx.x; i < sz; i += blockDim.x) g_perm[start + i] = sv[i];
}

// ---------------- final: gate + 256->10 GEMV + sigmoid ------------------------
__global__ void k_final(const float* __restrict__ wl, const float* __restrict__ bl,
                        float* __restrict__ out) {
    __shared__ float swl[HC * NOUT];
    for (int i = threadIdx.x; i < HC * NOUT; i += blockDim.x) swl[i] = wl[i];
    __syncthreads();
    int pos = blockIdx.x * 8 + (threadIdx.x >> 5);
    int lane = threadIdx.x & 31;
    if (pos >= NN) return;
    int p = g_perm[pos];
    float ts = tanhf(g_score[p]);
    float acc[NOUT];
#pragma unroll
    for (int o = 0; o < NOUT; o++) acc[o] = 0.f;
    size_t base = (size_t)p * HC + lane * 8;
#pragma unroll
    for (int jj = 0; jj < 8; jj++) {
        float v = g_add[base + jj] * ts;
        const float* wrow = &swl[(lane * 8 + jj) * NOUT];
#pragma unroll
        for (int o = 0; o < NOUT; o++) acc[o] += v * wrow[o];
    }
#pragma unroll
    for (int s = 16; s > 0; s >>= 1)
#pragma unroll
        for (int o = 0; o < NOUT; o++) acc[o] += __shfl_xor_sync(0xFFFFFFFFu, acc[o], s);
    if (lane == 0) {
#pragma unroll
        for (int o = 0; o < NOUT; o++)
            out[(size_t)pos * NOUT + o] = 1.f / (1.f + expf(-(acc[o] + bl[o])));
    }
}

// ---------------- launch ------------------------------------------------------
extern "C" void kernel_launch(void* const* d_in, const int* in_sizes, int n_in,
                              void* d_out, int out_size) {
    const float* x     = (const float*)d_in[0];
    const int*   eidx  = (const int*)d_in[1];
    const int*   batch = (const int*)d_in[2];
    const float* ea    = (const float*)d_in[3];
    const float* W[3]  = {(const float*)d_in[4],  (const float*)d_in[10], (const float*)d_in[16]};
    const float* AS[3] = {(const float*)d_in[5],  (const float*)d_in[11], (const float*)d_in[17]};
    const float* AD[3] = {(const float*)d_in[6],  (const float*)d_in[12], (const float*)d_in[18]};
    const float* WE[3] = {(const float*)d_in[7],  (const float*)d_in[13], (const float*)d_in[19]};
    const float* AE[3] = {(const float*)d_in[8],  (const float*)d_in[14], (const float*)d_in[20]};
    const float* B[3]  = {(const float*)d_in[9],  (const float*)d_in[15], (const float*)d_in[21]};
    const float* wrel  = (const float*)d_in[22];
    const float* brel  = (const float*)d_in[23];
    const float* wroot = (const float*)d_in[24];
    const float* wl    = (const float*)d_in[25];
    const float* bl    = (const float*)d_in[26];

    const int* src = eidx;
    const int* dst = eidx + NE;

    float* px = nullptr;
    cudaGetSymbolAddress((void**)&px, g_x);

    const int T = 256;

    // prologue: deg + mean edge_attr
    k_init0<<<(NN * EDIM + T - 1) / T, T>>>();
    k_deg<<<(NE + T - 1) / T, T>>>(dst);
    k_measum<<<(NE * EDIM + T - 1) / T, T>>>(dst, ea);
    k_meadiv<<<(NN * EDIM + T - 1) / T, T>>>();

    for (int l = 0; l < 3; l++) {
        const float* X = (l == 0) ? x : px;
        int K = (l == 0) ? FIN : HC;
        k_weeff<<<1, 64>>>(WE[l], AE[l]);
        k_gemm<<<dim3(HC / 64, (NN + 63) / 64), T>>>(X, W[l], K);
        k_layerinit<<<(NN * HC + T - 1) / T, T>>>();
        k_alsd<<<NN / 8, T>>>(AS[l], AD[l]);
        k_alpha<<<(NEF + T - 1) / T, T>>>(src, dst, ea);
        k_exp<<<(NEF * NH + T - 1) / T, T>>>(dst);
        k_aggr<<<(NEF + 7) / 8, T>>>(src, dst);
        k_post<<<(NN * HC + T - 1) / T, T>>>(B[l], l == 0);
    }

    // SAGPool score
    k_tr<<<NN / 8, T>>>(wrel, brel, wroot);
    k_scoreedge<<<(NE + T - 1) / T, T>>>(src, dst);

    // per-graph sort + final head
    k_gstart<<<(NN + T - 1) / T, T>>>(batch);
    k_sort<<<NGRP, 512>>>();
    k_final<<<(NN + 7) / 8, T>>>(wl, bl, (float*)d_out);
}

// round 2
// speedup vs baseline: 1.0087x; 1.0087x over previous
#include <cuda_runtime.h>
#include <math.h>
#include <float.h>

#define NN   50000
#define NE   400000
#define NEF  450000    // NE + NN self loops
#define FIN  128
#define HC   256
#define NH   4
#define CD   64
#define EDIM 16
#define NGRP 64
#define NOUT 10

// ---------------- scratch (device globals; no allocation allowed) ----------
static __device__ __align__(16) float g_x[NN * HC];     // layer input (layers 2,3)
static __device__ __align__(16) float g_h[NN * HC];     // h = X @ W
static __device__ __align__(16) float g_agg[NN * HC];   // aggregation target
static __device__ __align__(16) float g_add[NN * HC];   // residual accumulator
static __device__ float g_mea[NN * EDIM];               // mean edge_attr per dst
static __device__ float g_deg[NN];
static __device__ float g_als[NN * NH];
static __device__ float g_ald[NN * NH];
static __device__ float g_m[NN * NH];
static __device__ float g_den[NN * NH];
static __device__ float g_alpha[(size_t)NEF * NH];
static __device__ float g_weeff[EDIM * NH];
static __device__ float g_t[NN];
static __device__ float g_score[NN];
static __device__ int   g_gstart[NGRP + 1];
static __device__ int   g_perm[NN];

// ---------------- helpers ---------------------------------------------------
__device__ __forceinline__ float atomicMaxF(float* addr, float v) {
    int* ia = (int*)addr;
    int old = *ia;
    while (__int_as_float(old) < v) {
        int assumed = old;
        old = atomicCAS(ia, assumed, __float_as_int(v));
        if (old == assumed) break;
    }
    return __int_as_float(old);
}

// ---------------- prologue: degree + mean edge_attr -------------------------
__global__ void k_init0() {
    int i = blockIdx.x * blockDim.x + threadIdx.x;
    if (i < NN * EDIM) g_mea[i] = 0.f;
    if (i < NN) g_deg[i] = 0.f;
}
__global__ void k_deg(const int* __restrict__ dst) {
    int e = blockIdx.x * blockDim.x + threadIdx.x;
    if (e < NE) atomicAdd(&g_deg[dst[e]], 1.f);
}
__global__ void k_measum(const int* __restrict__ dst, const float* __restrict__ ea) {
    int i = blockIdx.x * blockDim.x + threadIdx.x;
    if (i >= NE * EDIM) return;
    int e = i >> 4, j = i & 15;
    atomicAdd(&g_mea[dst[e] * EDIM + j], ea[i]);
}
__global__ void k_meadiv() {
    int i = blockIdx.x * blockDim.x + threadIdx.x;
    if (i >= NN * EDIM) return;
    g_mea[i] /= fmaxf(g_deg[i >> 4], 1.f);
}

// ---------------- per-layer init --------------------------------------------
__global__ void k_layerinit() {
    int i = blockIdx.x * blockDim.x + threadIdx.x;
    if (i < NN * HC) g_agg[i] = 0.f;
    if (i < NN * NH) { g_m[i] = -FLT_MAX; g_den[i] = 0.f; }
}

// ---------------- GEMM: g_h = A[M,K] @ W[K,HC] ------------------------------
__global__ void k_gemm(const float* __restrict__ A, const float* __restrict__ W, int K) {
    const int BM = 64, BN = 64, BK = 16;
    __shared__ float As[BK][BM];
    __shared__ float Bs[BK][BN];
    int bx = blockIdx.x;        // column tile (HC/64 = 4)
    int by = blockIdx.y;        // row tile
    int tid = threadIdx.x;
    int tx = tid & 15, ty = tid >> 4;
    int rowBase = by * BM;
    int a_r = tid >> 2, a_c = (tid & 3) * 4;
    int b_r = tid >> 4, b_c = (tid & 15) * 4;
    float acc[4][4] = {};
    for (int k0 = 0; k0 < K; k0 += BK) {
        float4 av = make_float4(0.f, 0.f, 0.f, 0.f);
        int gr = rowBase + a_r;
        if (gr < NN) av = *(const float4*)&A[(size_t)gr * K + k0 + a_c];
        As[a_c + 0][a_r] = av.x; As[a_c + 1][a_r] = av.y;
        As[a_c + 2][a_r] = av.z; As[a_c + 3][a_r] = av.w;
        float4 bv = *(const float4*)&W[(size_t)(k0 + b_r) * HC + bx * BN + b_c];
        *(float4*)&Bs[b_r][b_c] = bv;
        __syncthreads();
#pragma unroll
        for (int kk = 0; kk < BK; kk++) {
            float ar[4], br[4];
#pragma unroll
            for (int i = 0; i < 4; i++) ar[i] = As[kk][ty * 4 + i];
#pragma unroll
            for (int j = 0; j < 4; j++) br[j] = Bs[kk][tx * 4 + j];
#pragma unroll
            for (int i = 0; i < 4; i++)
#pragma unroll
                for (int j = 0; j < 4; j++) acc[i][j] += ar[i] * br[j];
        }
        __syncthreads();
    }
#pragma unroll
    for (int i = 0; i < 4; i++) {
        int gr = rowBase + ty * 4 + i;
        if (gr < NN) {
            float4 v = make_float4(acc[i][0], acc[i][1], acc[i][2], acc[i][3]);
            *(float4*)&g_h[(size_t)gr * HC + bx * BN + tx * 4] = v;
        }
    }
}

// ---------------- effective edge weights: weeff[d][h] = sum_c We[d,h*C+c]*ae[h,c]
__global__ void k_weeff(const float* __restrict__ We, const float* __restrict__ ae) {
    int tid = threadIdx.x;
    if (tid >= EDIM * NH) return;
    int d = tid >> 2, h = tid & 3;
    float s = 0.f;
    for (int c = 0; c < CD; c++) s += We[d * HC + h * CD + c] * ae[h * CD + c];
    g_weeff[d * NH + h] = s;
}

// ---------------- per-node attention logits ---------------------------------
__global__ void k_alsd(const float* __restrict__ as_, const float* __restrict__ ad_) {
    int n = (blockIdx.x * blockDim.x + threadIdx.x) >> 5;
    int lane = threadIdx.x & 31;
    if (n >= NN) return;
    size_t base = (size_t)n * HC;
#pragma unroll
    for (int h = 0; h < NH; h++) {
        int o = h * CD + lane;
        float vs = g_h[base + o] * as_[o] + g_h[base + o + 32] * as_[o + 32];
        float vd = g_h[base + o] * ad_[o] + g_h[base + o + 32] * ad_[o + 32];
#pragma unroll
        for (int s = 16; s > 0; s >>= 1) {
            vs += __shfl_xor_sync(0xFFFFFFFFu, vs, s);
            vd += __shfl_xor_sync(0xFFFFFFFFu, vd, s);
        }
        if (lane == 0) { g_als[n * NH + h] = vs; g_ald[n * NH + h] = vd; }
    }
}

// ---------------- edge logits + segment max ---------------------------------
__global__ void k_alpha(const int* __restrict__ src, const int* __restrict__ dst,
                        const float* __restrict__ ea) {
    int e = blockIdx.x * blockDim.x + threadIdx.x;
    if (e >= NEF) return;
    int s, d;
    const float* eap;
    if (e < NE) { s = src[e]; d = dst[e]; eap = ea + (size_t)e * EDIM; }
    else        { s = d = e - NE; eap = g_mea + (size_t)(e - NE) * EDIM; }
    float ale[NH] = {0.f, 0.f, 0.f, 0.f};
#pragma unroll
    for (int dd = 0; dd < EDIM; dd++) {
        float v = eap[dd];
#pragma unroll
        for (int h = 0; h < NH; h++) ale[h] += v * g_weeff[dd * NH + h];
    }
#pragma unroll
    for (int h = 0; h < NH; h++) {
        float a = g_als[s * NH + h] + g_ald[d * NH + h] + ale[h];
        a = (a > 0.f) ? a : 0.2f * a;
        g_alpha[(size_t)e * NH + h] = a;
        atomicMaxF(&g_m[d * NH + h], a);
    }
}

// ---------------- exp + segment sum ------------------------------------------
__global__ void k_exp(const int* __restrict__ dst) {
    int i = blockIdx.x * blockDim.x + threadIdx.x;
    if (i >= NEF * NH) return;
    int e = i >> 2, h = i & 3;
    int d = (e < NE) ? dst[e] : (e - NE);
    float ex = expf(g_alpha[i] - g_m[d * NH + h]);
    g_alpha[i] = ex;
    atomicAdd(&g_den[d * NH + h], ex);
}

// ---------------- weighted scatter aggregation (warp per edge) --------------
__global__ void k_aggr(const int* __restrict__ src, const int* __restrict__ dst) {
    int e = (blockIdx.x * blockDim.x + threadIdx.x) >> 5;
    int lane = threadIdx.x & 31;
    if (e >= NEF) return;
    int s, d;
    if (e < NE) { s = src[e]; d = dst[e]; } else { s = d = e - NE; }
    int hh = lane >> 3;
    float w = g_alpha[(size_t)e * NH + hh] / (g_den[d * NH + hh] + 1e-16f);
    const float4* hp = (const float4*)&g_h[(size_t)s * HC + lane * 8];
    float4 v0 = hp[0], v1 = hp[1];
    float* op = &g_agg[(size_t)d * HC + lane * 8];
    atomicAdd(op + 0, v0.x * w); atomicAdd(op + 1, v0.y * w);
    atomicAdd(op + 2, v0.z * w); atomicAdd(op + 3, v0.w * w);
    atomicAdd(op + 4, v1.x * w); atomicAdd(op + 5, v1.y * w);
    atomicAdd(op + 6, v1.z * w); atomicAdd(op + 7, v1.w * w);
}

// ---------------- bias + relu + residual ------------------------------------
__global__ void k_post(const float* __restrict__ b, int first) {
    int i = blockIdx.x * blockDim.x + threadIdx.x;
    if (i >= NN * HC) return;
    float v = g_agg[i] + b[i & (HC - 1)];
    v = fmaxf(v, 0.f);
    g_x[i] = v;
    g_add[i] = first ? v : (g_add[i] + v);
}

// ---------------- SAGPool score ----------------------------------------------
__global__ void k_tr(const float* __restrict__ wrel, const float* __restrict__ brel,
                     const float* __restrict__ wroot) {
    int n = (blockIdx.x * blockDim.x + threadIdx.x) >> 5;
    int lane = threadIdx.x & 31;
    if (n >= NN) return;
    size_t base = (size_t)n * HC;
    float t = 0.f, r = 0.f;
#pragma unroll
    for (int k = 0; k < 8; k++) {
        int c = lane + 32 * k;
        float v = g_add[base + c];
        t += v * wrel[c];
        r += v * wroot[c];
    }
#pragma unroll
    for (int s = 16; s > 0; s >>= 1) {
        t += __shfl_xor_sync(0xFFFFFFFFu, t, s);
        r += __shfl_xor_sync(0xFFFFFFFFu, r, s);
    }
    if (lane == 0) { g_t[n] = t; g_score[n] = r + brel[0]; }
}
__global__ void k_scoreedge(const int* __restrict__ src, const int* __restrict__ dst) {
    int e = blockIdx.x * blockDim.x + threadIdx.x;
    if (e < NE) atomicAdd(&g_score[dst[e]], g_t[src[e]]);
}

// ---------------- group boundaries (batch is sorted) --------------------------
__global__ void k_gstart(const int* __restrict__ batch) {
    int n = blockIdx.x * blockDim.x + threadIdx.x;
    if (n >= NN) return;
    int b = batch[n];
    int prev = (n == 0) ? -1 : batch[n - 1];
    for (int g = prev + 1; g <= b; g++) g_gstart[g] = n;
    if (n == NN - 1) {
        for (int g = b + 1; g <= NGRP; g++) g_gstart[g] = NN;
    }
}

// ---------------- per-group bitonic sort (descending score, tie: asc index) --
#define SORTP 2048
__global__ void k_sort() {
    __shared__ float sk[SORTP];
    __shared__ int   sv[SORTP];
    int g = blockIdx.x;
    int start = g_gstart[g], end = g_gstart[g + 1];
    int sz = end - start;
    if (sz > SORTP) sz = SORTP;  // cannot happen at these sizes
    for (int i = threadIdx.x; i < SORTP; i += blockDim.x) {
        if (i < sz) { sk[i] = g_score[start + i]; sv[i] = start + i; }
        else        { sk[i] = -FLT_MAX; sv[i] = 0x7FFFFFFF; }
    }
    __syncthreads();
    for (int k = 2; k <= SORTP; k <<= 1) {
        for (int j = k >> 1; j > 0; j >>= 1) {
            for (int i = threadIdx.x; i < SORTP; i += blockDim.x) {
                int ixj = i ^ j;
                if (ixj > i) {
                    float ki = sk[i], kj = sk[ixj];
                    int vi = sv[i], vj = sv[ixj];
                    bool before = (kj > ki) || (kj == ki && vj < vi);
                    bool dir = ((i & k) == 0);
                    if (before == dir) {
                        sk[i] = kj; sk[ixj] = ki;
                        sv[i] = vj; sv[ixj] = vi;
                    }
                }
            }
            __syncthreads();
        }
    }
    for (int i = threadIdx.x; i < sz; i += blockDim.x) g_perm[start + i] = sv[i];
}

// ---------------- final: gate + 256->10 GEMV + sigmoid ------------------------
__global__ void k_final(const float* __restrict__ wl, const float* __restrict__ bl,
                        float* __restrict__ out) {
    __shared__ float swl[HC * NOUT];
    for (int i = threadIdx.x; i < HC * NOUT; i += blockDim.x) swl[i] = wl[i];
    __syncthreads();
    int pos = blockIdx.x * 8 + (threadIdx.x >> 5);
    int lane = threadIdx.x & 31;
    if (pos >= NN) return;
    int p = g_perm[pos];
    float ts = tanhf(g_score[p]);
    float acc[NOUT];
#pragma unroll
    for (int o = 0; o < NOUT; o++) acc[o] = 0.f;
    size_t base = (size_t)p * HC + lane * 8;
#pragma unroll
    for (int jj = 0; jj < 8; jj++) {
        float v = g_add[base + jj] * ts;
        const float* wrow = &swl[(lane * 8 + jj) * NOUT];
#pragma unroll
        for (int o = 0; o < NOUT; o++) acc[o] += v * wrow[o];
    }
#pragma unroll
    for (int s = 16; s > 0; s >>= 1)
#pragma unroll
        for (int o = 0; o < NOUT; o++) acc[o] += __shfl_xor_sync(0xFFFFFFFFu, acc[o], s);
    if (lane == 0) {
#pragma unroll
        for (int o = 0; o < NOUT; o++)
            out[(size_t)pos * NOUT + o] = 1.f / (1.f + expf(-(acc[o] + bl[o])));
    }
}

// ---------------- launch ------------------------------------------------------
extern "C" void kernel_launch(void* const* d_in, const int* in_sizes, int n_in,
                              void* d_out, int out_size) {
    const float* x     = (const float*)d_in[0];
    const int*   eidx  = (const int*)d_in[1];
    const int*   batch = (const int*)d_in[2];
    const float* ea    = (const float*)d_in[3];
    const float* W[3]  = {(const float*)d_in[4],  (const float*)d_in[10], (const float*)d_in[16]};
    const float* AS[3] = {(const float*)d_in[5],  (const float*)d_in[11], (const float*)d_in[17]};
    const float* AD[3] = {(const float*)d_in[6],  (const float*)d_in[12], (const float*)d_in[18]};
    const float* WE[3] = {(const float*)d_in[7],  (const float*)d_in[13], (const float*)d_in[19]};
    const float* AE[3] = {(const float*)d_in[8],  (const float*)d_in[14], (const float*)d_in[20]};
    const float* B[3]  = {(const float*)d_in[9],  (const float*)d_in[15], (const float*)d_in[21]};
    const float* wrel  = (const float*)d_in[22];
    const float* brel  = (const float*)d_in[23];
    const float* wroot = (const float*)d_in[24];
    const float* wl    = (const float*)d_in[25];
    const float* bl    = (const float*)d_in[26];

    const int* src = eidx;
    const int* dst = eidx + NE;

    float* px = nullptr;
    cudaGetSymbolAddress((void**)&px, g_x);

    const int T = 256;

    // prologue: deg + mean edge_attr
    k_init0<<<(NN * EDIM + T - 1) / T, T>>>();
    k_deg<<<(NE + T - 1) / T, T>>>(dst);
    k_measum<<<(NE * EDIM + T - 1) / T, T>>>(dst, ea);
    k_meadiv<<<(NN * EDIM + T - 1) / T, T>>>();

    for (int l = 0; l < 3; l++) {
        const float* X = (l == 0) ? x : px;
        int K = (l == 0) ? FIN : HC;
        k_weeff<<<1, 64>>>(WE[l], AE[l]);
        k_gemm<<<dim3(HC / 64, (NN + 63) / 64), T>>>(X, W[l], K);
        k_layerinit<<<(NN * HC + T - 1) / T, T>>>();
        k_alsd<<<NN / 8, T>>>(AS[l], AD[l]);
        k_alpha<<<(NEF + T - 1) / T, T>>>(src, dst, ea);
        k_exp<<<(NEF * NH + T - 1) / T, T>>>(dst);
        k_aggr<<<(NEF + 7) / 8, T>>>(src, dst);
        k_post<<<(NN * HC + T - 1) / T, T>>>(B[l], l == 0);
    }

    // SAGPool score
    k_tr<<<NN / 8, T>>>(wrel, brel, wroot);
    k_scoreedge<<<(NE + T - 1) / T, T>>>(src, dst);

    // per-graph sort + final head
    k_gstart<<<(NN + T - 1) / T, T>>>(batch);
    k_sort<<<NGRP, 512>>>();
    k_final<<<(NN + 7) / 8, T>>>(wl, bl, (float*)d_out);
}

// round 3
// speedup vs baseline: 2.6419x; 2.6191x over previous
#include <cuda_runtime.h>
#include <math.h>
#include <float.h>

#define NN   50000
#define NE   400000
#define NEF  450000    // NE + NN self loops
#define FIN  128
#define HC   256
#define NH   4
#define CD   64
#define EDIM 16
#define NGRP 64
#define NOUT 10

// ---------------- scratch (device globals; no allocation allowed) ----------
static __device__ __align__(16) float g_x[NN * HC];     // layer input (layers 2,3)
static __device__ __align__(16) float g_h[NN * HC];     // h = X @ W
static __device__ __align__(16) float g_add[NN * HC];   // residual accumulator
static __device__ float g_mea[NN * EDIM];               // mean edge_attr per dst
static __device__ int   g_degi[NN];
static __device__ float g_als[NN * NH];
static __device__ float g_ald[NN * NH];
static __device__ __align__(16) float g_alpha[(size_t)NEF * NH];
static __device__ float g_weeff[EDIM * NH];
static __device__ float g_t[NN];
static __device__ float g_score[NN];
static __device__ int   g_gstart[NGRP + 1];
static __device__ int   g_perm[NN];
// CSR by destination (built once, reused for all 3 layers)
static __device__ int   g_rowstart[NN + 1];
static __device__ int   g_cursor[NN];
static __device__ int   g_csrsrc[NE];
static __device__ int   g_csre[NE];

// ---------------- prologue: zero + degree + mean edge_attr ------------------
__global__ void k_init0() {
    int i = blockIdx.x * blockDim.x + threadIdx.x;
    if (i < NN * EDIM) g_mea[i] = 0.f;
    if (i < NN) { g_degi[i] = 0; g_cursor[i] = 0; }
}
__global__ void k_deg(const int* __restrict__ dst) {
    int e = blockIdx.x * blockDim.x + threadIdx.x;
    if (e < NE) atomicAdd(&g_degi[dst[e]], 1);
}
__global__ void k_measum(const int* __restrict__ dst, const float* __restrict__ ea) {
    int i = blockIdx.x * blockDim.x + threadIdx.x;
    if (i >= NE * EDIM) return;
    int e = i >> 4, j = i & 15;
    atomicAdd(&g_mea[dst[e] * EDIM + j], ea[i]);
}
__global__ void k_meadiv() {
    int i = blockIdx.x * blockDim.x + threadIdx.x;
    if (i >= NN * EDIM) return;
    g_mea[i] /= fmaxf((float)g_degi[i >> 4], 1.f);
}

// ---------------- single-block exclusive scan of degrees --------------------
__global__ void k_scan() {
    __shared__ int buf[1024];
    __shared__ int soff;
    int tid = threadIdx.x;
    if (tid == 0) soff = 0;
    __syncthreads();
    for (int chunk = 0; chunk < NN; chunk += 1024) {
        int i = chunk + tid;
        int v = (i < NN) ? g_degi[i] : 0;
        buf[tid] = v;
        __syncthreads();
        for (int s = 1; s < 1024; s <<= 1) {
            int t = (tid >= s) ? buf[tid - s] : 0;
            __syncthreads();
            buf[tid] += t;
            __syncthreads();
        }
        int off = soff;
        if (i < NN) g_rowstart[i] = off + buf[tid] - v;
        __syncthreads();
        if (tid == 1023) soff = off + buf[1023];
        __syncthreads();
    }
    if (tid == 0) g_rowstart[NN] = NE;
}

__global__ void k_fill(const int* __restrict__ src, const int* __restrict__ dst) {
    int e = blockIdx.x * blockDim.x + threadIdx.x;
    if (e >= NE) return;
    int d = dst[e];
    int pos = atomicAdd(&g_cursor[d], 1);
    int idx = g_rowstart[d] + pos;
    g_csrsrc[idx] = src[e];
    g_csre[idx] = e;
}

// ---------------- GEMM: g_h = A[M,K] @ W[K,HC], 128x128x8, 8x8 micro --------
__global__ void __launch_bounds__(256, 2) k_gemm(const float* __restrict__ A,
                                                 const float* __restrict__ W, int K) {
    const int BM = 128, BN = 128, BK = 8;
    __shared__ float As[BK][BM];
    __shared__ float Bs[BK][BN];
    int bx = blockIdx.x;            // 0..1
    int by = blockIdx.y;
    int tid = threadIdx.x;
    int rowBase = by * BM;
    int arow = tid >> 1, acol = (tid & 1) * 4;
    int brow = tid >> 5, bcol = (tid & 31) * 4;
    int tx = tid & 15, ty = tid >> 4;
    float acc[8][8] = {};
    for (int k0 = 0; k0 < K; k0 += BK) {
        float4 av = make_float4(0.f, 0.f, 0.f, 0.f);
        int gr = rowBase + arow;
        if (gr < NN) av = *(const float4*)&A[(size_t)gr * K + k0 + acol];
        As[acol + 0][arow] = av.x; As[acol + 1][arow] = av.y;
        As[acol + 2][arow] = av.z; As[acol + 3][arow] = av.w;
        float4 bv = *(const float4*)&W[(size_t)(k0 + brow) * HC + bx * BN + bcol];
        *(float4*)&Bs[brow][bcol] = bv;
        __syncthreads();
#pragma unroll
        for (int kk = 0; kk < BK; kk++) {
            float ar[8], br[8];
            *(float4*)&ar[0] = *(float4*)&As[kk][ty * 8];
            *(float4*)&ar[4] = *(float4*)&As[kk][ty * 8 + 4];
            *(float4*)&br[0] = *(float4*)&Bs[kk][tx * 8];
            *(float4*)&br[4] = *(float4*)&Bs[kk][tx * 8 + 4];
#pragma unroll
            for (int i = 0; i < 8; i++)
#pragma unroll
                for (int j = 0; j < 8; j++) acc[i][j] += ar[i] * br[j];
        }
        __syncthreads();
    }
#pragma unroll
    for (int i = 0; i < 8; i++) {
        int gr = rowBase + ty * 8 + i;
        if (gr < NN) {
            *(float4*)&g_h[(size_t)gr * HC + bx * BN + tx * 8]     = *(float4*)&acc[i][0];
            *(float4*)&g_h[(size_t)gr * HC + bx * BN + tx * 8 + 4] = *(float4*)&acc[i][4];
        }
    }
}

// ---------------- effective edge weights ------------------------------------
__global__ void k_weeff(const float* __restrict__ We, const float* __restrict__ ae) {
    int tid = threadIdx.x;
    if (tid >= EDIM * NH) return;
    int d = tid >> 2, h = tid & 3;
    float s = 0.f;
    for (int c = 0; c < CD; c++) s += We[d * HC + h * CD + c] * ae[h * CD + c];
    g_weeff[d * NH + h] = s;
}

// ---------------- per-node attention logits ---------------------------------
__global__ void k_alsd(const float* __restrict__ as_, const float* __restrict__ ad_) {
    int n = (blockIdx.x * blockDim.x + threadIdx.x) >> 5;
    int lane = threadIdx.x & 31;
    if (n >= NN) return;
    size_t base = (size_t)n * HC;
#pragma unroll
    for (int h = 0; h < NH; h++) {
        int o = h * CD + lane;
        float vs = g_h[base + o] * as_[o] + g_h[base + o + 32] * as_[o + 32];
        float vd = g_h[base + o] * ad_[o] + g_h[base + o + 32] * ad_[o + 32];
#pragma unroll
        for (int s = 16; s > 0; s >>= 1) {
            vs += __shfl_xor_sync(0xFFFFFFFFu, vs, s);
            vd += __shfl_xor_sync(0xFFFFFFFFu, vd, s);
        }
        if (lane == 0) { g_als[n * NH + h] = vs; g_ald[n * NH + h] = vd; }
    }
}

// ---------------- edge logits (leaky relu'd) --------------------------------
__global__ void k_alpha(const int* __restrict__ src, const int* __restrict__ dst,
                        const float* __restrict__ ea) {
    int e = blockIdx.x * blockDim.x + threadIdx.x;
    if (e >= NEF) return;
    int s, d;
    const float* eap;
    if (e < NE) { s = src[e]; d = dst[e]; eap = ea + (size_t)e * EDIM; }
    else        { s = d = e - NE; eap = g_mea + (size_t)(e - NE) * EDIM; }
    float ale[NH] = {0.f, 0.f, 0.f, 0.f};
#pragma unroll
    for (int dd = 0; dd < EDIM; dd++) {
        float v = eap[dd];
#pragma unroll
        for (int h = 0; h < NH; h++) ale[h] += v * g_weeff[dd * NH + h];
    }
    float4 out;
    float* op = (float*)&out;
#pragma unroll
    for (int h = 0; h < NH; h++) {
        float a = g_als[s * NH + h] + g_ald[d * NH + h] + ale[h];
        op[h] = (a > 0.f) ? a : 0.2f * a;
    }
    *(float4*)&g_alpha[(size_t)e * NH] = out;
}

// ---------------- gather aggregation: warp per dst, online softmax ----------
__global__ void k_gather(const float* __restrict__ b, int first) {
    int d = blockIdx.x * (blockDim.x >> 5) + (threadIdx.x >> 5);
    int lane = threadIdx.x & 31;
    if (d >= NN) return;
    int h = lane >> 3;
    float acc[8] = {};
    float m = -FLT_MAX, den = 0.f;
    int beg = g_rowstart[d], end = g_rowstart[d + 1];
    for (int i = beg; i < end; i++) {
        int s = g_csrsrc[i];
        int e = g_csre[i];
        float a = g_alpha[(size_t)e * NH + h];
        float mnew = fmaxf(m, a);
        float scale = __expf(m - mnew);
        float ex = __expf(a - mnew);
        den = den * scale + ex;
        const float4* hp = (const float4*)&g_h[(size_t)s * HC + lane * 8];
        float4 v0 = hp[0], v1 = hp[1];
        acc[0] = acc[0] * scale + ex * v0.x; acc[1] = acc[1] * scale + ex * v0.y;
        acc[2] = acc[2] * scale + ex * v0.z; acc[3] = acc[3] * scale + ex * v0.w;
        acc[4] = acc[4] * scale + ex * v1.x; acc[5] = acc[5] * scale + ex * v1.y;
        acc[6] = acc[6] * scale + ex * v1.z; acc[7] = acc[7] * scale + ex * v1.w;
        m = mnew;
    }
    {   // self loop (src = dst = d)
        float a = g_alpha[(size_t)(NE + d) * NH + h];
        float mnew = fmaxf(m, a);
        float scale = __expf(m - mnew);
        float ex = __expf(a - mnew);
        den = den * scale + ex;
        const float4* hp = (const float4*)&g_h[(size_t)d * HC + lane * 8];
        float4 v0 = hp[0], v1 = hp[1];
        acc[0] = acc[0] * scale + ex * v0.x; acc[1] = acc[1] * scale + ex * v0.y;
        acc[2] = acc[2] * scale + ex * v0.z; acc[3] = acc[3] * scale + ex * v0.w;
        acc[4] = acc[4] * scale + ex * v1.x; acc[5] = acc[5] * scale + ex * v1.y;
        acc[6] = acc[6] * scale + ex * v1.z; acc[7] = acc[7] * scale + ex * v1.w;
    }
    float inv = 1.f / (den + 1e-16f);
    int col = lane * 8;
    float o[8];
#pragma unroll
    for (int j = 0; j < 8; j++) {
        float v = acc[j] * inv + b[col + j];
        o[j] = fmaxf(v, 0.f);
    }
    size_t base = (size_t)d * HC + col;
    *(float4*)&g_x[base]     = *(float4*)&o[0];
    *(float4*)&g_x[base + 4] = *(float4*)&o[4];
    if (first) {
        *(float4*)&g_add[base]     = *(float4*)&o[0];
        *(float4*)&g_add[base + 4] = *(float4*)&o[4];
    } else {
        float4 a0 = *(float4*)&g_add[base], a1 = *(float4*)&g_add[base + 4];
        a0.x += o[0]; a0.y += o[1]; a0.z += o[2]; a0.w += o[3];
        a1.x += o[4]; a1.y += o[5]; a1.z += o[6]; a1.w += o[7];
        *(float4*)&g_add[base]     = a0;
        *(float4*)&g_add[base + 4] = a1;
    }
}

// ---------------- SAGPool score ----------------------------------------------
__global__ void k_tr(const float* __restrict__ wrel, const float* __restrict__ brel,
                     const float* __restrict__ wroot) {
    int n = (blockIdx.x * blockDim.x + threadIdx.x) >> 5;
    int lane = threadIdx.x & 31;
    if (n >= NN) return;
    size_t base = (size_t)n * HC;
    float t = 0.f, r = 0.f;
#pragma unroll
    for (int k = 0; k < 8; k++) {
        int c = lane + 32 * k;
        float v = g_add[base + c];
        t += v * wrel[c];
        r += v * wroot[c];
    }
#pragma unroll
    for (int s = 16; s > 0; s >>= 1) {
        t += __shfl_xor_sync(0xFFFFFFFFu, t, s);
        r += __shfl_xor_sync(0xFFFFFFFFu, r, s);
    }
    if (lane == 0) { g_t[n] = t; g_score[n] = r + brel[0]; }
}
__global__ void k_scoreedge(const int* __restrict__ src, const int* __restrict__ dst) {
    int e = blockIdx.x * blockDim.x + threadIdx.x;
    if (e < NE) atomicAdd(&g_score[dst[e]], g_t[src[e]]);
}

// ---------------- group boundaries (batch is sorted) --------------------------
__global__ void k_gstart(const int* __restrict__ batch) {
    int n = blockIdx.x * blockDim.x + threadIdx.x;
    if (n >= NN) return;
    int b = batch[n];
    int prev = (n == 0) ? -1 : batch[n - 1];
    for (int g = prev + 1; g <= b; g++) g_gstart[g] = n;
    if (n == NN - 1) {
        for (int g = b + 1; g <= NGRP; g++) g_gstart[g] = NN;
    }
}

// ---------------- per-group bitonic sort (descending score, tie: asc index) --
#define SORTP 2048
__global__ void k_sort() {
    __shared__ float sk[SORTP];
    __shared__ int   sv[SORTP];
    int g = blockIdx.x;
    int start = g_gstart[g], end = g_gstart[g + 1];
    int sz = end - start;
    if (sz > SORTP) sz = SORTP;
    for (int i = threadIdx.x; i < SORTP; i += blockDim.x) {
        if (i < sz) { sk[i] = g_score[start + i]; sv[i] = start + i; }
        else        { sk[i] = -FLT_MAX; sv[i] = 0x7FFFFFFF; }
    }
    __syncthreads();
    for (int k = 2; k <= SORTP; k <<= 1) {
        for (int j = k >> 1; j > 0; j >>= 1) {
            for (int i = threadIdx.x; i < SORTP; i += blockDim.x) {
                int ixj = i ^ j;
                if (ixj > i) {
                    float ki = sk[i], kj = sk[ixj];
                    int vi = sv[i], vj = sv[ixj];
                    bool before = (kj > ki) || (kj == ki && vj < vi);
                    bool dir = ((i & k) == 0);
                    if (before == dir) {
                        sk[i] = kj; sk[ixj] = ki;
                        sv[i] = vj; sv[ixj] = vi;
                    }
                }
            }
            __syncthreads();
        }
    }
    for (int i = threadIdx.x; i < sz; i += blockDim.x) g_perm[start + i] = sv[i];
}

// ---------------- final: gate + 256->10 GEMV + sigmoid ------------------------
__global__ void k_final(const float* __restrict__ wl, const float* __restrict__ bl,
                        float* __restrict__ out) {
    __shared__ float swl[HC * NOUT];
    for (int i = threadIdx.x; i < HC * NOUT; i += blockDim.x) swl[i] = wl[i];
    __syncthreads();
    int pos = blockIdx.x * 8 + (threadIdx.x >> 5);
    int lane = threadIdx.x & 31;
    if (pos >= NN) return;
    int p = g_perm[pos];
    float ts = tanhf(g_score[p]);
    float acc[NOUT];
#pragma unroll
    for (int o = 0; o < NOUT; o++) acc[o] = 0.f;
    size_t base = (size_t)p * HC + lane * 8;
#pragma unroll
    for (int jj = 0; jj < 8; jj++) {
        float v = g_add[base + jj] * ts;
        const float* wrow = &swl[(lane * 8 + jj) * NOUT];
#pragma unroll
        for (int o = 0; o < NOUT; o++) acc[o] += v * wrow[o];
    }
#pragma unroll
    for (int s = 16; s > 0; s >>= 1)
#pragma unroll
        for (int o = 0; o < NOUT; o++) acc[o] += __shfl_xor_sync(0xFFFFFFFFu, acc[o], s);
    if (lane == 0) {
#pragma unroll
        for (int o = 0; o < NOUT; o++)
            out[(size_t)pos * NOUT + o] = 1.f / (1.f + expf(-(acc[o] + bl[o])));
    }
}

// ---------------- launch ------------------------------------------------------
extern "C" void kernel_launch(void* const* d_in, const int* in_sizes, int n_in,
                              void* d_out, int out_size) {
    const float* x     = (const float*)d_in[0];
    const int*   eidx  = (const int*)d_in[1];
    const int*   batch = (const int*)d_in[2];
    const float* ea    = (const float*)d_in[3];
    const float* W[3]  = {(const float*)d_in[4],  (const float*)d_in[10], (const float*)d_in[16]};
    const float* AS[3] = {(const float*)d_in[5],  (const float*)d_in[11], (const float*)d_in[17]};
    const float* AD[3] = {(const float*)d_in[6],  (const float*)d_in[12], (const float*)d_in[18]};
    const float* WE[3] = {(const float*)d_in[7],  (const float*)d_in[13], (const float*)d_in[19]};
    const float* AE[3] = {(const float*)d_in[8],  (const float*)d_in[14], (const float*)d_in[20]};
    const float* B[3]  = {(const float*)d_in[9],  (const float*)d_in[15], (const float*)d_in[21]};
    const float* wrel  = (const float*)d_in[22];
    const float* brel  = (const float*)d_in[23];
    const float* wroot = (const float*)d_in[24];
    const float* wl    = (const float*)d_in[25];
    const float* bl    = (const float*)d_in[26];

    const int* src = eidx;
    const int* dst = eidx + NE;

    float* px = nullptr;
    cudaGetSymbolAddress((void**)&px, g_x);

    const int T = 256;

    // prologue: deg + mean edge_attr + CSR (reused across layers)
    k_init0<<<(NN * EDIM + T - 1) / T, T>>>();
    k_deg<<<(NE + T - 1) / T, T>>>(dst);
    k_measum<<<(NE * EDIM + T - 1) / T, T>>>(dst, ea);
    k_meadiv<<<(NN * EDIM + T - 1) / T, T>>>();
    k_scan<<<1, 1024>>>();
    k_fill<<<(NE + T - 1) / T, T>>>(src, dst);

    for (int l = 0; l < 3; l++) {
        const float* X = (l == 0) ? x : px;
        int K = (l == 0) ? FIN : HC;
        k_weeff<<<1, 64>>>(WE[l], AE[l]);
        k_gemm<<<dim3(HC / 128, (NN + 127) / 128), T>>>(X, W[l], K);
        k_alsd<<<NN / 8, T>>>(AS[l], AD[l]);
        k_alpha<<<(NEF + T - 1) / T, T>>>(src, dst, ea);
        k_gather<<<(NN + 7) / 8, T>>>(B[l], l == 0);
    }

    // SAGPool score
    k_tr<<<NN / 8, T>>>(wrel, brel, wroot);
    k_scoreedge<<<(NE + T - 1) / T, T>>>(src, dst);

    // per-graph sort + final head
    k_gstart<<<(NN + T - 1) / T, T>>>(batch);
    k_sort<<<NGRP, 512>>>();
    k_final<<<(NN + 7) / 8, T>>>(wl, bl, (float*)d_out);
}

// round 4
// speedup vs baseline: 3.1630x; 1.1973x over previous
#include <cuda_runtime.h>
#include <cuda_bf16.h>
#include <math.h>
#include <float.h>
#include <stdint.h>

#define NN   50000
#define NE   400000
#define NEF  450000    // NE + NN self loops
#define FIN  128
#define HC   256
#define NH   4
#define CD   64
#define EDIM 16
#define NGRP 64
#define NOUT 10

// ---------------- scratch (device globals; no allocation allowed) ----------
static __device__ __align__(16) float g_x[NN * HC];     // layer input (layers 2,3)
static __device__ __align__(16) float g_h[NN * HC];     // h = X @ W
static __device__ __align__(16) float g_add[NN * HC];   // residual accumulator
static __device__ float g_mea[NN * EDIM];               // mean edge_attr per dst
static __device__ int   g_degi[NN];
static __device__ float g_als[NN * NH];
static __device__ float g_ald[NN * NH];
static __device__ __align__(16) float g_alpha[(size_t)NEF * NH];
static __device__ float g_weeff[EDIM * NH];
static __device__ float g_t[NN];
static __device__ float g_score[NN];
static __device__ int   g_gstart[NGRP + 1];
static __device__ int   g_perm[NN];
// CSR by destination (built once, reused for all 3 layers)
static __device__ int   g_rowstart[NN + 1];
static __device__ int   g_cursor[NN];
static __device__ int   g_csrsrc[NE];
static __device__ int   g_csre[NE];

// ---------------- prologue: zero + degree + mean edge_attr ------------------
__global__ void k_init0() {
    int i = blockIdx.x * blockDim.x + threadIdx.x;
    if (i < NN * EDIM) g_mea[i] = 0.f;
    if (i < NN) { g_degi[i] = 0; g_cursor[i] = 0; }
}
__global__ void k_deg(const int* __restrict__ dst) {
    int e = blockIdx.x * blockDim.x + threadIdx.x;
    if (e < NE) atomicAdd(&g_degi[dst[e]], 1);
}
__global__ void k_measum(const int* __restrict__ dst, const float* __restrict__ ea) {
    int i = blockIdx.x * blockDim.x + threadIdx.x;
    if (i >= NE * EDIM) return;
    int e = i >> 4, j = i & 15;
    atomicAdd(&g_mea[dst[e] * EDIM + j], ea[i]);
}
__global__ void k_meadiv() {
    int i = blockIdx.x * blockDim.x + threadIdx.x;
    if (i >= NN * EDIM) return;
    g_mea[i] /= fmaxf((float)g_degi[i >> 4], 1.f);
}

// ---------------- single-block exclusive scan of degrees --------------------
__global__ void k_scan() {
    __shared__ int buf[1024];
    __shared__ int soff;
    int tid = threadIdx.x;
    if (tid == 0) soff = 0;
    __syncthreads();
    for (int chunk = 0; chunk < NN; chunk += 1024) {
        int i = chunk + tid;
        int v = (i < NN) ? g_degi[i] : 0;
        buf[tid] = v;
        __syncthreads();
        for (int s = 1; s < 1024; s <<= 1) {
            int t = (tid >= s) ? buf[tid - s] : 0;
            __syncthreads();
            buf[tid] += t;
            __syncthreads();
        }
        int off = soff;
        if (i < NN) g_rowstart[i] = off + buf[tid] - v;
        __syncthreads();
        if (tid == 1023) soff = off + buf[1023];
        __syncthreads();
    }
    if (tid == 0) g_rowstart[NN] = NE;
}

__global__ void k_fill(const int* __restrict__ src, const int* __restrict__ dst) {
    int e = blockIdx.x * blockDim.x + threadIdx.x;
    if (e >= NE) return;
    int d = dst[e];
    int pos = atomicAdd(&g_cursor[d], 1);
    int idx = g_rowstart[d] + pos;
    g_csrsrc[idx] = src[e];
    g_csre[idx] = e;
}

// ---------------- tensor-core GEMM: g_h = A[M,K] @ W[K,HC] ------------------
// bf16x3 split (hi/lo), mma.sync m16n8k16, fp32 accumulate.
__device__ __forceinline__ void ldsm_x4(uint32_t& r0, uint32_t& r1, uint32_t& r2,
                                        uint32_t& r3, uint32_t addr) {
    asm volatile("ldmatrix.sync.aligned.m8n8.x4.shared.b16 {%0,%1,%2,%3}, [%4];"
                 : "=r"(r0), "=r"(r1), "=r"(r2), "=r"(r3) : "r"(addr));
}
__device__ __forceinline__ void ldsm_x2t(uint32_t& r0, uint32_t& r1, uint32_t addr) {
    asm volatile("ldmatrix.sync.aligned.m8n8.x2.trans.shared.b16 {%0,%1}, [%2];"
                 : "=r"(r0), "=r"(r1) : "r"(addr));
}
__device__ __forceinline__ void mma_bf16(float* d, uint32_t a0, uint32_t a1,
                                         uint32_t a2, uint32_t a3,
                                         uint32_t b0, uint32_t b1) {
    asm volatile(
        "mma.sync.aligned.m16n8k16.row.col.f32.bf16.bf16.f32 "
        "{%0,%1,%2,%3}, {%4,%5,%6,%7}, {%8,%9}, {%0,%1,%2,%3};"
        : "+f"(d[0]), "+f"(d[1]), "+f"(d[2]), "+f"(d[3])
        : "r"(a0), "r"(a1), "r"(a2), "r"(a3), "r"(b0), "r"(b1));
}
__device__ __forceinline__ uint32_t pack2(float a, float b) {
    __nv_bfloat162 t = __floats2bfloat162_rn(a, b);
    return *(uint32_t*)&t;
}

#define ASTR 40
#define BSTR 136
__global__ void __launch_bounds__(256, 1) k_gemm(const float* __restrict__ A,
                                                 const float* __restrict__ W, int K) {
    __shared__ __align__(16) unsigned short As_hi[128 * ASTR];
    __shared__ __align__(16) unsigned short As_lo[128 * ASTR];
    __shared__ __align__(16) unsigned short Bs_hi[32 * BSTR];
    __shared__ __align__(16) unsigned short Bs_lo[32 * BSTR];

    const int tid = threadIdx.x;
    const int lane = tid & 31;
    const int wid = tid >> 5;
    const int wm = (wid >> 2) * 64;
    const int wn = (wid & 3) * 32;
    const int rowBase = blockIdx.y * 128;
    const int n0 = blockIdx.x * 128;

    const int am = tid >> 1, ak = (tid & 1) * 16;   // A staging
    const int bk = tid >> 3, bn = (tid & 7) * 16;   // B staging

    float acc[4][4][4];
#pragma unroll
    for (int i = 0; i < 4; i++)
#pragma unroll
        for (int j = 0; j < 4; j++)
#pragma unroll
            for (int q = 0; q < 4; q++) acc[i][j][q] = 0.f;

    const uint32_t sAhi = (uint32_t)__cvta_generic_to_shared(As_hi);
    const uint32_t sAlo = (uint32_t)__cvta_generic_to_shared(As_lo);
    const uint32_t sBhi = (uint32_t)__cvta_generic_to_shared(Bs_hi);
    const uint32_t sBlo = (uint32_t)__cvta_generic_to_shared(Bs_lo);

    for (int k0 = 0; k0 < K; k0 += 32) {
        // ---- stage A (128x32) with hi/lo split ----
        {
            float v[16];
            int gm = rowBase + am;
            if (gm < NN) {
                const float4* p = (const float4*)&A[(size_t)gm * K + k0 + ak];
#pragma unroll
                for (int q = 0; q < 4; q++) *(float4*)&v[q * 4] = p[q];
            } else {
#pragma unroll
                for (int q = 0; q < 16; q++) v[q] = 0.f;
            }
            float hi[16], lo[16];
#pragma unroll
            for (int q = 0; q < 16; q++) {
                hi[q] = __bfloat162float(__float2bfloat16_rn(v[q]));
                lo[q] = v[q] - hi[q];
            }
            unsigned short* ph = &As_hi[am * ASTR + ak];
            unsigned short* pl = &As_lo[am * ASTR + ak];
#pragma unroll
            for (int q = 0; q < 8; q++) {
                *(uint32_t*)&ph[q * 2] = pack2(hi[q * 2], hi[q * 2 + 1]);
                *(uint32_t*)&pl[q * 2] = pack2(lo[q * 2], lo[q * 2 + 1]);
            }
        }
        // ---- stage B (32x128) with hi/lo split ----
        {
            float v[16];
            const float4* p = (const float4*)&W[(size_t)(k0 + bk) * HC + n0 + bn];
#pragma unroll
            for (int q = 0; q < 4; q++) *(float4*)&v[q * 4] = p[q];
            float hi[16], lo[16];
#pragma unroll
            for (int q = 0; q < 16; q++) {
                hi[q] = __bfloat162float(__float2bfloat16_rn(v[q]));
                lo[q] = v[q] - hi[q];
            }
            unsigned short* ph = &Bs_hi[bk * BSTR + bn];
            unsigned short* pl = &Bs_lo[bk * BSTR + bn];
#pragma unroll
            for (int q = 0; q < 8; q++) {
                *(uint32_t*)&ph[q * 2] = pack2(hi[q * 2], hi[q * 2 + 1]);
                *(uint32_t*)&pl[q * 2] = pack2(lo[q * 2], lo[q * 2 + 1]);
            }
        }
        __syncthreads();

#pragma unroll
        for (int ks = 0; ks < 32; ks += 16) {
            uint32_t ahi[4][4], alo[4][4], bhi[4][2], blo[4][2];
            int arow = lane & 15;
            int acol = ks + ((lane >> 4) << 3);
#pragma unroll
            for (int i = 0; i < 4; i++) {
                uint32_t off = ((wm + i * 16 + arow) * ASTR + acol) * 2;
                ldsm_x4(ahi[i][0], ahi[i][1], ahi[i][2], ahi[i][3], sAhi + off);
                ldsm_x4(alo[i][0], alo[i][1], alo[i][2], alo[i][3], sAlo + off);
            }
            int brow = ks + (lane & 7) + ((lane >> 3) & 1) * 8;
#pragma unroll
            for (int j = 0; j < 4; j++) {
                uint32_t off = (brow * BSTR + wn + j * 8) * 2;
                ldsm_x2t(bhi[j][0], bhi[j][1], sBhi + off);
                ldsm_x2t(blo[j][0], blo[j][1], sBlo + off);
            }
#pragma unroll
            for (int i = 0; i < 4; i++)
#pragma unroll
                for (int j = 0; j < 4; j++) {
                    mma_bf16(acc[i][j], ahi[i][0], ahi[i][1], ahi[i][2], ahi[i][3],
                             bhi[j][0], bhi[j][1]);
                    mma_bf16(acc[i][j], ahi[i][0], ahi[i][1], ahi[i][2], ahi[i][3],
                             blo[j][0], blo[j][1]);
                    mma_bf16(acc[i][j], alo[i][0], alo[i][1], alo[i][2], alo[i][3],
                             bhi[j][0], bhi[j][1]);
                }
        }
        __syncthreads();
    }

    // ---- epilogue ----
#pragma unroll
    for (int i = 0; i < 4; i++) {
        int r0 = rowBase + wm + i * 16 + (lane >> 2);
#pragma unroll
        for (int j = 0; j < 4; j++) {
            int c = n0 + wn + j * 8 + (lane & 3) * 2;
            if (r0 < NN)
                *(float2*)&g_h[(size_t)r0 * HC + c] = make_float2(acc[i][j][0], acc[i][j][1]);
            if (r0 + 8 < NN)
                *(float2*)&g_h[(size_t)(r0 + 8) * HC + c] = make_float2(acc[i][j][2], acc[i][j][3]);
        }
    }
}

// ---------------- effective edge weights ------------------------------------
__global__ void k_weeff(const float* __restrict__ We, const float* __restrict__ ae) {
    int tid = threadIdx.x;
    if (tid >= EDIM * NH) return;
    int d = tid >> 2, h = tid & 3;
    float s = 0.f;
    for (int c = 0; c < CD; c++) s += We[d * HC + h * CD + c] * ae[h * CD + c];
    g_weeff[d * NH + h] = s;
}

// ---------------- per-node attention logits ---------------------------------
__global__ void k_alsd(const float* __restrict__ as_, const float* __restrict__ ad_) {
    int n = (blockIdx.x * blockDim.x + threadIdx.x) >> 5;
    int lane = threadIdx.x & 31;
    if (n >= NN) return;
    size_t base = (size_t)n * HC;
#pragma unroll
    for (int h = 0; h < NH; h++) {
        int o = h * CD + lane;
        float vs = g_h[base + o] * as_[o] + g_h[base + o + 32] * as_[o + 32];
        float vd = g_h[base + o] * ad_[o] + g_h[base + o + 32] * ad_[o + 32];
#pragma unroll
        for (int s = 16; s > 0; s >>= 1) {
            vs += __shfl_xor_sync(0xFFFFFFFFu, vs, s);
            vd += __shfl_xor_sync(0xFFFFFFFFu, vd, s);
        }
        if (lane == 0) { g_als[n * NH + h] = vs; g_ald[n * NH + h] = vd; }
    }
}

// ---------------- edge logits (leaky relu'd) --------------------------------
__global__ void k_alpha(const int* __restrict__ src, const int* __restrict__ dst,
                        const float* __restrict__ ea) {
    int e = blockIdx.x * blockDim.x + threadIdx.x;
    if (e >= NEF) return;
    int s, d;
    const float* eap;
    if (e < NE) { s = src[e]; d = dst[e]; eap = ea + (size_t)e * EDIM; }
    else        { s = d = e - NE; eap = g_mea + (size_t)(e - NE) * EDIM; }
    float ale[NH] = {0.f, 0.f, 0.f, 0.f};
#pragma unroll
    for (int dd = 0; dd < EDIM; dd++) {
        float v = eap[dd];
#pragma unroll
        for (int h = 0; h < NH; h++) ale[h] += v * g_weeff[dd * NH + h];
    }
    float4 out;
    float* op = (float*)&out;
#pragma unroll
    for (int h = 0; h < NH; h++) {
        float a = g_als[s * NH + h] + g_ald[d * NH + h] + ale[h];
        op[h] = (a > 0.f) ? a : 0.2f * a;
    }
    *(float4*)&g_alpha[(size_t)e * NH] = out;
}

// ---------------- gather aggregation: warp per dst, online softmax ----------
__global__ void k_gather(const float* __restrict__ b, int first) {
    int d = blockIdx.x * (blockDim.x >> 5) + (threadIdx.x >> 5);
    int lane = threadIdx.x & 31;
    if (d >= NN) return;
    int h = lane >> 3;
    float acc[8] = {};
    float m = -FLT_MAX, den = 0.f;
    int beg = g_rowstart[d], end = g_rowstart[d + 1];
    for (int i = beg; i < end; i++) {
        int s = g_csrsrc[i];
        int e = g_csre[i];
        float a = g_alpha[(size_t)e * NH + h];
        float mnew = fmaxf(m, a);
        float scale = __expf(m - mnew);
        float ex = __expf(a - mnew);
        den = den * scale + ex;
        const float4* hp = (const float4*)&g_h[(size_t)s * HC + lane * 8];
        float4 v0 = hp[0], v1 = hp[1];
        acc[0] = acc[0] * scale + ex * v0.x; acc[1] = acc[1] * scale + ex * v0.y;
        acc[2] = acc[2] * scale + ex * v0.z; acc[3] = acc[3] * scale + ex * v0.w;
        acc[4] = acc[4] * scale + ex * v1.x; acc[5] = acc[5] * scale + ex * v1.y;
        acc[6] = acc[6] * scale + ex * v1.z; acc[7] = acc[7] * scale + ex * v1.w;
        m = mnew;
    }
    {   // self loop (src = dst = d)
        float a = g_alpha[(size_t)(NE + d) * NH + h];
        float mnew = fmaxf(m, a);
        float scale = __expf(m - mnew);
        float ex = __expf(a - mnew);
        den = den * scale + ex;
        const float4* hp = (const float4*)&g_h[(size_t)d * HC + lane * 8];
        float4 v0 = hp[0], v1 = hp[1];
        acc[0] = acc[0] * scale + ex * v0.x; acc[1] = acc[1] * scale + ex * v0.y;
        acc[2] = acc[2] * scale + ex * v0.z; acc[3] = acc[3] * scale + ex * v0.w;
        acc[4] = acc[4] * scale + ex * v1.x; acc[5] = acc[5] * scale + ex * v1.y;
        acc[6] = acc[6] * scale + ex * v1.z; acc[7] = acc[7] * scale + ex * v1.w;
    }
    float inv = 1.f / (den + 1e-16f);
    int col = lane * 8;
    float o[8];
#pragma unroll
    for (int j = 0; j < 8; j++) {
        float v = acc[j] * inv + b[col + j];
        o[j] = fmaxf(v, 0.f);
    }
    size_t base = (size_t)d * HC + col;
    *(float4*)&g_x[base]     = *(float4*)&o[0];
    *(float4*)&g_x[base + 4] = *(float4*)&o[4];
    if (first) {
        *(float4*)&g_add[base]     = *(float4*)&o[0];
        *(float4*)&g_add[base + 4] = *(float4*)&o[4];
    } else {
        float4 a0 = *(float4*)&g_add[base], a1 = *(float4*)&g_add[base + 4];
        a0.x += o[0]; a0.y += o[1]; a0.z += o[2]; a0.w += o[3];
        a1.x += o[4]; a1.y += o[5]; a1.z += o[6]; a1.w += o[7];
        *(float4*)&g_add[base]     = a0;
        *(float4*)&g_add[base + 4] = a1;
    }
}

// ---------------- SAGPool score ----------------------------------------------
__global__ void k_tr(const float* __restrict__ wrel, const float* __restrict__ brel,
                     const float* __restrict__ wroot) {
    int n = (blockIdx.x * blockDim.x + threadIdx.x) >> 5;
    int lane = threadIdx.x & 31;
    if (n >= NN) return;
    size_t base = (size_t)n * HC;
    float t = 0.f, r = 0.f;
#pragma unroll
    for (int k = 0; k < 8; k++) {
        int c = lane + 32 * k;
        float v = g_add[base + c];
        t += v * wrel[c];
        r += v * wroot[c];
    }
#pragma unroll
    for (int s = 16; s > 0; s >>= 1) {
        t += __shfl_xor_sync(0xFFFFFFFFu, t, s);
        r += __shfl_xor_sync(0xFFFFFFFFu, r, s);
    }
    if (lane == 0) { g_t[n] = t; g_score[n] = r + brel[0]; }
}
__global__ void k_scoreedge(const int* __restrict__ src, const int* __restrict__ dst) {
    int e = blockIdx.x * blockDim.x + threadIdx.x;
    if (e < NE) atomicAdd(&g_score[dst[e]], g_t[src[e]]);
}

// ---------------- group boundaries (batch is sorted) --------------------------
__global__ void k_gstart(const int* __restrict__ batch) {
    int n = blockIdx.x * blockDim.x + threadIdx.x;
    if (n >= NN) return;
    int b = batch[n];
    int prev = (n == 0) ? -1 : batch[n - 1];
    for (int g = prev + 1; g <= b; g++) g_gstart[g] = n;
    if (n == NN - 1) {
        for (int g = b + 1; g <= NGRP; g++) g_gstart[g] = NN;
    }
}

// ---------------- per-group bitonic sort (descending score, tie: asc index) --
#define SORTP 2048
__global__ void k_sort() {
    __shared__ float sk[SORTP];
    __shared__ int   sv[SORTP];
    int g = blockIdx.x;
    int start = g_gstart[g], end = g_gstart[g + 1];
    int sz = end - start;
    if (sz > SORTP) sz = SORTP;
    for (int i = threadIdx.x; i < SORTP; i += blockDim.x) {
        if (i < sz) { sk[i] = g_score[start + i]; sv[i] = start + i; }
        else        { sk[i] = -FLT_MAX; sv[i] = 0x7FFFFFFF; }
    }
    __syncthreads();
    for (int k = 2; k <= SORTP; k <<= 1) {
        for (int j = k >> 1; j > 0; j >>= 1) {
            for (int i = threadIdx.x; i < SORTP; i += blockDim.x) {
                int ixj = i ^ j;
                if (ixj > i) {
                    float ki = sk[i], kj = sk[ixj];
                    int vi = sv[i], vj = sv[ixj];
                    bool before = (kj > ki) || (kj == ki && vj < vi);
                    bool dir = ((i & k) == 0);
                    if (before == dir) {
                        sk[i] = kj; sk[ixj] = ki;
                        sv[i] = vj; sv[ixj] = vi;
                    }
                }
            }
            __syncthreads();
        }
    }
    for (int i = threadIdx.x; i < sz; i += blockDim.x) g_perm[start + i] = sv[i];
}

// ---------------- final: gate + 256->10 GEMV + sigmoid ------------------------
__global__ void k_final(const float* __restrict__ wl, const float* __restrict__ bl,
                        float* __restrict__ out) {
    __shared__ float swl[HC * NOUT];
    for (int i = threadIdx.x; i < HC * NOUT; i += blockDim.x) swl[i] = wl[i];
    __syncthreads();
    int pos = blockIdx.x * 8 + (threadIdx.x >> 5);
    int lane = threadIdx.x & 31;
    if (pos >= NN) return;
    int p = g_perm[pos];
    float ts = tanhf(g_score[p]);
    float acc[NOUT];
#pragma unroll
    for (int o = 0; o < NOUT; o++) acc[o] = 0.f;
    size_t base = (size_t)p * HC + lane * 8;
#pragma unroll
    for (int jj = 0; jj < 8; jj++) {
        float v = g_add[base + jj] * ts;
        const float* wrow = &swl[(lane * 8 + jj) * NOUT];
#pragma unroll
        for (int o = 0; o < NOUT; o++) acc[o] += v * wrow[o];
    }
#pragma unroll
    for (int s = 16; s > 0; s >>= 1)
#pragma unroll
        for (int o = 0; o < NOUT; o++) acc[o] += __shfl_xor_sync(0xFFFFFFFFu, acc[o], s);
    if (lane == 0) {
#pragma unroll
        for (int o = 0; o < NOUT; o++)
            out[(size_t)pos * NOUT + o] = 1.f / (1.f + expf(-(acc[o] + bl[o])));
    }
}

// ---------------- launch ------------------------------------------------------
extern "C" void kernel_launch(void* const* d_in, const int* in_sizes, int n_in,
                              void* d_out, int out_size) {
    const float* x     = (const float*)d_in[0];
    const int*   eidx  = (const int*)d_in[1];
    const int*   batch = (const int*)d_in[2];
    const float* ea    = (const float*)d_in[3];
    const float* W[3]  = {(const float*)d_in[4],  (const float*)d_in[10], (const float*)d_in[16]};
    const float* AS[3] = {(const float*)d_in[5],  (const float*)d_in[11], (const float*)d_in[17]};
    const float* AD[3] = {(const float*)d_in[6],  (const float*)d_in[12], (const float*)d_in[18]};
    const float* WE[3] = {(const float*)d_in[7],  (const float*)d_in[13], (const float*)d_in[19]};
    const float* AE[3] = {(const float*)d_in[8],  (const float*)d_in[14], (const float*)d_in[20]};
    const float* B[3]  = {(const float*)d_in[9],  (const float*)d_in[15], (const float*)d_in[21]};
    const float* wrel  = (const float*)d_in[22];
    const float* brel  = (const float*)d_in[23];
    const float* wroot = (const float*)d_in[24];
    const float* wl    = (const float*)d_in[25];
    const float* bl    = (const float*)d_in[26];

    const int* src = eidx;
    const int* dst = eidx + NE;

    float* px = nullptr;
    cudaGetSymbolAddress((void**)&px, g_x);

    const int T = 256;

    // prologue: deg + mean edge_attr + CSR (reused across layers)
    k_init0<<<(NN * EDIM + T - 1) / T, T>>>();
    k_deg<<<(NE + T - 1) / T, T>>>(dst);
    k_measum<<<(NE * EDIM + T - 1) / T, T>>>(dst, ea);
    k_meadiv<<<(NN * EDIM + T - 1) / T, T>>>();
    k_scan<<<1, 1024>>>();
    k_fill<<<(NE + T - 1) / T, T>>>(src, dst);

    for (int l = 0; l < 3; l++) {
        const float* X = (l == 0) ? x : px;
        int K = (l == 0) ? FIN : HC;
        k_weeff<<<1, 64>>>(WE[l], AE[l]);
        k_gemm<<<dim3(HC / 128, (NN + 127) / 128), T>>>(X, W[l], K);
        k_alsd<<<NN / 8, T>>>(AS[l], AD[l]);
        k_alpha<<<(NEF + T - 1) / T, T>>>(src, dst, ea);
        k_gather<<<(NN + 7) / 8, T>>>(B[l], l == 0);
    }

    // SAGPool score
    k_tr<<<NN / 8, T>>>(wrel, brel, wroot);
    k_scoreedge<<<(NE + T - 1) / T, T>>>(src, dst);

    // per-graph sort + final head
    k_gstart<<<(NN + T - 1) / T, T>>>(batch);
    k_sort<<<NGRP, 512>>>();
    k_final<<<(NN + 7) / 8, T>>>(wl, bl, (float*)d_out);
}